// round 1
// baseline (speedup 1.0000x reference)
#include <cuda_runtime.h>

#define BATCH 128
#define DIM   4096
#define NG    3

// ---- packed f32x2 helpers (Blackwell) ----
__device__ __forceinline__ unsigned long long pack2(float lo, float hi) {
    unsigned long long r;
    asm("mov.b64 %0, {%1, %2};" : "=l"(r) : "f"(lo), "f"(hi));
    return r;
}
__device__ __forceinline__ void unpack2(unsigned long long v, float& lo, float& hi) {
    asm("mov.b64 {%0, %1}, %2;" : "=f"(lo), "=f"(hi) : "l"(v));
}
__device__ __forceinline__ unsigned long long ffma2(unsigned long long a,
                                                    unsigned long long b,
                                                    unsigned long long c) {
    unsigned long long d;
    asm("fma.rn.f32x2 %0, %1, %2, %3;" : "=l"(d) : "l"(a), "l"(b), "l"(c));
    return d;
}

// SMEM padding: conflict-free for stride-1 and stride-16 fiber access,
// single 2-way conflict for stride-256.
__device__ __forceinline__ int phys(int i) { return i + (i >> 4); }

__global__ __launch_bounds__(256, 1)
void ulayer_kernel(const float* __restrict__ thetas,
                   const float* __restrict__ evecs,
                   const float* __restrict__ evals,
                   const float* __restrict__ sreal,
                   const float* __restrict__ simag,
                   float* __restrict__ out)
{
    __shared__ float sr[4352];           // padded real state (4096 + pad)
    __shared__ float si[4352];           // padded imag state
    __shared__ float4 g4[NG * 256];      // gates packed (Ur, Ur, -Ui, Ui)

    // scratch overlay inside sr (used only before the state is loaded)
    float* Vs = sr;          // 16 rows, stride 17 -> 272 floats
    float* cs = sr + 288;    // 3*16 cos values
    float* sn = sr + 336;    // 3*16 sin values

    const int t = threadIdx.x;
    const int b = blockIdx.x;

    // ---- stage V and sincos into scratch ----
    {
        int j = t >> 4, m = t & 15;
        Vs[j * 17 + m] = evecs[t];               // V[j][m]
    }
    if (t < NG * 16) {
        int g = t >> 4, m = t & 15;
        float ang = thetas[g] * evals[m];
        float s, c;
        sincosf(ang, &s, &c);
        cs[g * 16 + m] = c;
        sn[g * 16 + m] = s;
    }
    __syncthreads();

    // ---- build the three 16x16 gates: U = V diag(cos - i sin) V^T ----
    {
        int j = t >> 4, k = t & 15;
        #pragma unroll
        for (int g = 0; g < NG; g++) {
            float ar = 0.f, ai = 0.f;            // ar = Ur, ai = sum(p*sin) so Ui = -ai
            #pragma unroll
            for (int m = 0; m < 16; m++) {
                float p = Vs[j * 17 + m] * Vs[k * 17 + m];
                ar += p * cs[g * 16 + m];
                ai += p * sn[g * 16 + m];
            }
            // packed (Ur, Ur, -Ui, Ui) = (ar, ar, ai, -ai)
            g4[g * 256 + j * 16 + k] = make_float4(ar, ar, ai, -ai);
        }
    }
    __syncthreads();   // gates done reading scratch before state overwrites it

    // ---- load state into padded SMEM ----
    const float* srg = sreal + b * DIM;
    const float* sig = simag + b * DIM;
    #pragma unroll
    for (int w = 0; w < 16; w++) {
        int i = t + w * 256;
        int ip = phys(i);
        sr[ip] = srg[i];
        si[ip] = sig[i];
    }
    __syncthreads();

    // ---- three in-place 16x16 complex contractions ----
    // index i = a*256 + b16*16 + c ; U0 acts on a, U1 on b16, U2 on c
    #pragma unroll 1
    for (int step = 0; step < 3; step++) {
        int base, stride, g;
        if (step == 0)      { base = t * 16;                       stride = 1;   g = 2; }
        else if (step == 1) { base = (t >> 4) * 256 + (t & 15);    stride = 16;  g = 1; }
        else                { base = (t >> 4) * 16  + (t & 15);    stride = 256; g = 0; }

        const ulonglong2* G =
            reinterpret_cast<const ulonglong2*>(g4 + g * 256);

        unsigned long long acc[16];
        #pragma unroll
        for (int k = 0; k < 16; k++) acc[k] = 0ULL;   // (0.f, 0.f)

        #pragma unroll
        for (int kp = 0; kp < 16; kp++) {
            int ip = phys(base + kp * stride);
            float xr = sr[ip], xi = si[ip];
            unsigned long long xp = pack2(xr, xi);    // (xr, xi)
            unsigned long long xs = pack2(xi, xr);    // (xi, xr)
            #pragma unroll
            for (int k = 0; k < 16; k++) {
                ulonglong2 u = G[k * 16 + kp];        // LDS.128, warp-uniform broadcast
                acc[k] = ffma2(u.x, xp, acc[k]);      // += (Ur*xr, Ur*xi)
                acc[k] = ffma2(u.y, xs, acc[k]);      // += (-Ui*xi, Ui*xr)
            }
        }

        // thread-private fiber: safe to write in place, then sync for next step
        #pragma unroll
        for (int k = 0; k < 16; k++) {
            int ip = phys(base + k * stride);
            float lo, hi;
            unpack2(acc[k], lo, hi);
            sr[ip] = lo;
            si[ip] = hi;
        }
        __syncthreads();
    }

    // ---- write output: [2, BATCH, DIM] ----
    float* outr = out + b * DIM;
    float* outi = out + (size_t)BATCH * DIM + b * DIM;
    #pragma unroll
    for (int w = 0; w < 16; w++) {
        int i = t + w * 256;
        int ip = phys(i);
        outr[i] = sr[ip];
        outi[i] = si[ip];
    }
}

extern "C" void kernel_launch(void* const* d_in, const int* in_sizes, int n_in,
                              void* d_out, int out_size) {
    const float* thetas = (const float*)d_in[0];
    const float* evecs  = (const float*)d_in[1];
    const float* evals  = (const float*)d_in[2];
    const float* sreal  = (const float*)d_in[3];
    const float* simag  = (const float*)d_in[4];
    ulayer_kernel<<<BATCH, 256>>>(thetas, evecs, evals, sreal, simag, (float*)d_out);
}